// round 1
// baseline (speedup 1.0000x reference)
#include <cuda_runtime.h>
#include <math.h>

#define Nn 50000
#define Ee 800000
#define KIN 256
#define NC 448          // 0:256 feat | 256:320 z | 320:324 q | 324:328 p | 328:392 merge_x | 392:448 pad
#define SLOPE 0.2f

// ---------------- scratch (device globals; no allocation allowed) ----------------
__device__ float g_lin[Nn * NC];        // fused GEMM output, row stride 448
__device__ float g_Wc[KIN * NC];        // combined weight
__device__ float g_bias[NC];
__device__ float g_el[Nn * 4];
__device__ float g_er[Nn * 4];
__device__ int   g_deg[Nn];
__device__ int   g_off[Nn + 1];
__device__ int   g_cur[Nn];
__device__ int   g_csr[Ee];

// ---------------- weight prep: build combined [256 x 448] weight + bias ----------
__global__ void k_prep(const float* __restrict__ W_gat, const float* __restrict__ gate_m_W,
                       const float* __restrict__ gate_m_b, const float* __restrict__ gate_fn_W,
                       const float* __restrict__ merge_W, const float* __restrict__ merge_b) {
    int idx = blockIdx.x * blockDim.x + threadIdx.x;
    if (idx < KIN * NC) {
        int k = idx / NC, j = idx % NC;
        float v = 0.f;
        if (j < 256)      v = W_gat[k * 256 + j];
        else if (j < 320) v = gate_m_W[k * 64 + (j - 256)];
        else if (j < 324) v = gate_fn_W[k * 4 + (j - 320)];            // q: x part of gate
        else if (j < 328) v = gate_fn_W[(320 + k) * 4 + (j - 324)];    // p: mean_z part projected
        else if (j < 392) v = merge_W[k * 64 + (j - 328)];             // merge x-part
        g_Wc[idx] = v;
    }
    if (idx < NC) {
        float b = 0.f;
        if (idx >= 256 && idx < 320)      b = gate_m_b[idx - 256];
        else if (idx >= 328 && idx < 392) b = merge_b[idx - 328];
        g_bias[idx] = b;
    }
}

// ---------------- CSR build ----------------
__global__ void k_zero() {
    int i = blockIdx.x * blockDim.x + threadIdx.x;
    if (i < Nn) g_deg[i] = 0;
}

__global__ void k_deg(const int* __restrict__ dst) {
    int e = blockIdx.x * blockDim.x + threadIdx.x;
    if (e < Ee) atomicAdd(&g_deg[dst[e]], 1);
}

__global__ void k_scan() {  // single block, 1024 threads
    __shared__ int tmp[1024];
    __shared__ int carry_s;
    int tid = threadIdx.x;
    if (tid == 0) carry_s = 0;
    __syncthreads();
    for (int base = 0; base < Nn; base += 1024) {
        int i = base + tid;
        int v = (i < Nn) ? g_deg[i] : 0;
        tmp[tid] = v;
        __syncthreads();
#pragma unroll
        for (int off = 1; off < 1024; off <<= 1) {
            int t = (tid >= off) ? tmp[tid - off] : 0;
            __syncthreads();
            tmp[tid] += t;
            __syncthreads();
        }
        int incl = tmp[tid];
        int excl = incl - v;
        if (i < Nn) {
            int o = carry_s + excl;
            g_off[i] = o;
            g_cur[i] = o;
        }
        __syncthreads();
        if (tid == 1023) carry_s += incl;
        __syncthreads();
    }
    if (tid == 0) g_off[Nn] = carry_s;
}

__global__ void k_fill(const int* __restrict__ src, const int* __restrict__ dst) {
    int e = blockIdx.x * blockDim.x + threadIdx.x;
    if (e < Ee) {
        int pos = atomicAdd(&g_cur[dst[e]], 1);
        g_csr[pos] = src[e];
    }
}

// ---------------- fused GEMM: g_lin = x @ Wc + bias  (M=50000, K=256, N=448) -----
__global__ __launch_bounds__(256) void k_gemm(const float* __restrict__ x) {
    __shared__ float As[8][128];
    __shared__ float Bs[8][64];
    const int bCol = blockIdx.x * 64;
    const int bRow = blockIdx.y * 128;
    const int tid = threadIdx.x;
    const int tr = tid >> 4;    // 0..15 (row group)
    const int tc = tid & 15;    // 0..15 (col group)
    float acc[8][4];
#pragma unroll
    for (int i = 0; i < 8; i++)
#pragma unroll
        for (int j = 0; j < 4; j++) acc[i][j] = 0.f;

    const int amRow = tid >> 1;        // 0..127
    const int ak = (tid & 1) * 4;      // 0 or 4
    const int bk = tid >> 5;           // 0..7
    const int nb = (tid * 2) & 63;
    const int gmA = bRow + amRow;
    const float* xrow = x + (long long)gmA * KIN + ak;

    for (int k0 = 0; k0 < KIN; k0 += 8) {
        float4 av = make_float4(0.f, 0.f, 0.f, 0.f);
        if (gmA < Nn) av = *reinterpret_cast<const float4*>(xrow + k0);
        As[ak + 0][amRow] = av.x;
        As[ak + 1][amRow] = av.y;
        As[ak + 2][amRow] = av.z;
        As[ak + 3][amRow] = av.w;
        float2 bv = *reinterpret_cast<const float2*>(&g_Wc[(k0 + bk) * NC + bCol + nb]);
        Bs[bk][nb] = bv.x;
        Bs[bk][nb + 1] = bv.y;
        __syncthreads();
#pragma unroll
        for (int kk = 0; kk < 8; kk++) {
            float4 a0 = *reinterpret_cast<const float4*>(&As[kk][tr * 8]);
            float4 a1 = *reinterpret_cast<const float4*>(&As[kk][tr * 8 + 4]);
            float4 bq = *reinterpret_cast<const float4*>(&Bs[kk][tc * 4]);
            float a[8] = {a0.x, a0.y, a0.z, a0.w, a1.x, a1.y, a1.z, a1.w};
            float bb[4] = {bq.x, bq.y, bq.z, bq.w};
#pragma unroll
            for (int i = 0; i < 8; i++)
#pragma unroll
                for (int j = 0; j < 4; j++) acc[i][j] = fmaf(a[i], bb[j], acc[i][j]);
        }
        __syncthreads();
    }
#pragma unroll
    for (int i = 0; i < 8; i++) {
        int gm = bRow + tr * 8 + i;
        if (gm < Nn) {
#pragma unroll
            for (int j = 0; j < 4; j++) {
                int gc = bCol + tc * 4 + j;
                g_lin[gm * NC + gc] = acc[i][j] + g_bias[gc];
            }
        }
    }
}

// ---------------- el/er: per-node dot(feat, attn_l/attn_r) ----------------------
__global__ __launch_bounds__(256) void k_eler(const float* __restrict__ attn_l,
                                              const float* __restrict__ attn_r) {
    int gw = (blockIdx.x * blockDim.x + threadIdx.x) >> 5;
    int lane = threadIdx.x & 31;
    if (gw >= Nn) return;
    float al[8], ar[8];
#pragma unroll
    for (int k = 0; k < 8; k++) {
        al[k] = attn_l[lane + 32 * k];
        ar[k] = attn_r[lane + 32 * k];
    }
    float elp[4] = {0.f, 0.f, 0.f, 0.f};
    float erp[4] = {0.f, 0.f, 0.f, 0.f};
    const float* row = &g_lin[gw * NC];
#pragma unroll
    for (int k = 0; k < 8; k++) {
        float f = row[lane + 32 * k];
        int h = k >> 1;
        elp[h] = fmaf(f, al[k], elp[h]);
        erp[h] = fmaf(f, ar[k], erp[h]);
    }
#pragma unroll
    for (int h = 0; h < 4; h++) {
#pragma unroll
        for (int o = 16; o > 0; o >>= 1) {
            elp[h] += __shfl_xor_sync(0xffffffffu, elp[h], o);
            erp[h] += __shfl_xor_sync(0xffffffffu, erp[h], o);
        }
    }
    if (lane < 4) {
        g_el[gw * 4 + lane] = elp[lane];
        g_er[gw * 4 + lane] = erp[lane];
    }
}

// ---------------- main aggregation: warp per node, no float atomics ---------------
__global__ __launch_bounds__(256) void k_aggr(const float* __restrict__ gate_fn_W,
                                              const float* __restrict__ gate_fn_b,
                                              const float* __restrict__ merge_W,
                                              float* __restrict__ out) {
    __shared__ float sW2[64][64];   // merge_W rows 256..319
    __shared__ float sGm[64][4];    // gate_fn_W rows 256..319 (max_z part)
    __shared__ float sGated[8][64];
    int tid = threadIdx.x;
    for (int i = tid; i < 64 * 64; i += 256) ((float*)sW2)[i] = merge_W[256 * 64 + i];
    for (int i = tid; i < 64 * 4; i += 256) ((float*)sGm)[i] = gate_fn_W[256 * 4 + i];
    __syncthreads();

    int warp = tid >> 5, lane = tid & 31;
    int n = blockIdx.x * 8 + warp;
    if (n >= Nn) return;

    int start = g_off[n], end = g_off[n + 1];
    int deg = end - start;
    int lg = lane >> 2;    // edge group 0..7
    int lh = lane & 3;     // head
    float er_l = (lane < 4) ? g_er[n * 4 + lane] : 0.f;
    float er_h = __shfl_sync(0xffffffffu, er_l, lh);

    // ---- pass 1: z max (all lanes, 2 cols each) ----
    float zc0 = -INFINITY, zc1 = -INFINITY;
    for (int i = start; i < end; i++) {
        int s = g_csr[i];
        const float* row = &g_lin[s * NC];
        zc0 = fmaxf(zc0, row[256 + lane]);
        zc1 = fmaxf(zc1, row[288 + lane]);
    }
    if (deg == 0) { zc0 = 0.f; zc1 = 0.f; }

    // ---- pass 2 (grouped 8-way): e max per head + p sum ----
    float emax = -INFINITY, psum = 0.f;
    for (int i = start + lg; i < end; i += 8) {
        int s = g_csr[i];
        float e = g_el[s * 4 + lh] + er_h;
        e = e > 0.f ? e : SLOPE * e;
        emax = fmaxf(emax, e);
        psum += g_lin[s * NC + 324 + lh];
    }
    emax = fmaxf(emax, __shfl_xor_sync(0xffffffffu, emax, 4));
    emax = fmaxf(emax, __shfl_xor_sync(0xffffffffu, emax, 8));
    emax = fmaxf(emax, __shfl_xor_sync(0xffffffffu, emax, 16));
    psum += __shfl_xor_sync(0xffffffffu, psum, 4);
    psum += __shfl_xor_sync(0xffffffffu, psum, 8);
    psum += __shfl_xor_sync(0xffffffffu, psum, 16);
    float m_h = (emax > -INFINITY) ? emax : 0.f;

    // ---- pass 3 (grouped): softmax denominator ----
    float ssum = 0.f;
    for (int i = start + lg; i < end; i += 8) {
        int s = g_csr[i];
        float e = g_el[s * 4 + lh] + er_h;
        e = e > 0.f ? e : SLOPE * e;
        ssum += __expf(e - m_h);
    }
    ssum += __shfl_xor_sync(0xffffffffu, ssum, 4);
    ssum += __shfl_xor_sync(0xffffffffu, ssum, 8);
    ssum += __shfl_xor_sync(0xffffffffu, ssum, 16);
    float rcp = __frcp_rn(fmaxf(ssum, 1e-16f));

    // ---- pass 4: alpha-weighted feat accumulation (all lanes) ----
    float acc[8] = {0.f, 0.f, 0.f, 0.f, 0.f, 0.f, 0.f, 0.f};
    for (int i = start; i < end; i++) {
        int s = g_csr[i];
        float e = g_el[s * 4 + lh] + er_h;   // each lane computes for its head (redundant x8)
        e = e > 0.f ? e : SLOPE * e;
        float a = __expf(e - m_h) * rcp;
        float a4[4];
#pragma unroll
        for (int h = 0; h < 4; h++) a4[h] = __shfl_sync(0xffffffffu, a, h);
        const float* row = &g_lin[s * NC];
#pragma unroll
        for (int k = 0; k < 8; k++) acc[k] = fmaf(a4[k >> 1], row[lane + 32 * k], acc[k]);
    }

    // ---- gate: sigmoid(q + zmax@Wm + psum/deg + b) ----
    float red[4];
#pragma unroll
    for (int h = 0; h < 4; h++) red[h] = zc0 * sGm[lane][h] + zc1 * sGm[lane + 32][h];
#pragma unroll
    for (int h = 0; h < 4; h++) {
#pragma unroll
        for (int o = 16; o > 0; o >>= 1) red[h] += __shfl_xor_sync(0xffffffffu, red[h], o);
    }
    float red_h = (lh == 0) ? red[0] : (lh == 1) ? red[1] : (lh == 2) ? red[2] : red[3];
    float q_h = g_lin[n * NC + 320 + lh];
    float rdeg = 1.0f / (float)max(deg, 1);
    float pre = q_h + red_h + psum * rdeg + gate_fn_b[lh];
    float gate = 1.0f / (1.0f + __expf(-pre));
    float g4[4];
#pragma unroll
    for (int h = 0; h < 4; h++) g4[h] = __shfl_sync(0xffffffffu, gate, h);

    // ---- gated = mean over heads; stage to shared ----
    sGated[warp][lane]      = 0.25f * (g4[0] * acc[0] + g4[1] * acc[2] + g4[2] * acc[4] + g4[3] * acc[6]);
    sGated[warp][lane + 32] = 0.25f * (g4[0] * acc[1] + g4[1] * acc[3] + g4[2] * acc[5] + g4[3] * acc[7]);
    __syncwarp();

    // ---- merge: out = merge_x(+b) + gated @ W2 ----
    float o0 = g_lin[n * NC + 328 + lane];
    float o1 = g_lin[n * NC + 328 + 32 + lane];
#pragma unroll
    for (int op = 0; op < 64; op++) {
        float gv = sGated[warp][op];
        o0 = fmaf(gv, sW2[op][lane], o0);
        o1 = fmaf(gv, sW2[op][lane + 32], o1);
    }
    out[n * 64 + lane] = o0;
    out[n * 64 + 32 + lane] = o1;
}

// ---------------- launch ----------------
extern "C" void kernel_launch(void* const* d_in, const int* in_sizes, int n_in,
                              void* d_out, int out_size) {
    const float* x         = (const float*)d_in[0];
    const int*   src       = (const int*)d_in[1];
    const int*   dst       = (const int*)d_in[2];
    const float* W_gat     = (const float*)d_in[3];
    const float* attn_l    = (const float*)d_in[4];
    const float* attn_r    = (const float*)d_in[5];
    const float* gate_m_W  = (const float*)d_in[6];
    const float* gate_m_b  = (const float*)d_in[7];
    const float* gate_fn_W = (const float*)d_in[8];
    const float* gate_fn_b = (const float*)d_in[9];
    const float* merge_W   = (const float*)d_in[10];
    const float* merge_b   = (const float*)d_in[11];
    float* out = (float*)d_out;

    k_prep<<<(KIN * NC + 255) / 256, 256>>>(W_gat, gate_m_W, gate_m_b, gate_fn_W, merge_W, merge_b);
    k_zero<<<(Nn + 255) / 256, 256>>>();
    k_deg<<<(Ee + 255) / 256, 256>>>(dst);
    k_scan<<<1, 1024>>>();
    k_fill<<<(Ee + 255) / 256, 256>>>(src, dst);
    dim3 ggrid(NC / 64, (Nn + 127) / 128);
    k_gemm<<<ggrid, 256>>>(x);
    k_eler<<<(Nn * 32 + 255) / 256, 256>>>(attn_l, attn_r);
    k_aggr<<<(Nn + 7) / 8, 256>>>(gate_fn_W, gate_fn_b, merge_W, out);
}

// round 2
// speedup vs baseline: 1.2455x; 1.2455x over previous
#include <cuda_runtime.h>
#include <math.h>

#define Nn 50000
#define Ee 800000
#define KIN 256
#define NC 448   // 0:256 feat | 256:320 z | 320:324 q | 324:328 p | 328:392 merge_x | 392:396 el | 396:400 er | 400:448 pad
#define SLOPE 0.2f

// ---------------- scratch (device globals; no allocation allowed) ----------------
__device__ float g_lin[Nn * NC];
__device__ float g_Wc[KIN * NC];
__device__ float g_bias[NC];
__device__ int   g_deg[Nn];
__device__ int   g_off[Nn + 1];
__device__ int   g_cur[Nn];
__device__ int   g_csr[Ee];

// ---------------- helpers: packed f32x2 FMA ----------------
__device__ __forceinline__ unsigned long long dupf(float f) {
    unsigned long long r; unsigned u = __float_as_uint(f);
    asm("mov.b64 %0, {%1, %1};" : "=l"(r) : "r"(u));
    return r;
}
__device__ __forceinline__ void fma2(unsigned long long& acc, unsigned long long a, unsigned long long b) {
    asm("fma.rn.f32x2 %0, %1, %2, %0;" : "+l"(acc) : "l"(a), "l"(b));
}
__device__ __forceinline__ float2 unpack2(unsigned long long v) {
    unsigned lo, hi;
    asm("mov.b64 {%0, %1}, %2;" : "=r"(lo), "=r"(hi) : "l"(v));
    return make_float2(__uint_as_float(lo), __uint_as_float(hi));
}

// ---------------- weight prep: combined [256 x 448] weight + bias + deg zero -----
__global__ void k_prep(const float* __restrict__ W_gat, const float* __restrict__ gate_m_W,
                       const float* __restrict__ gate_m_b, const float* __restrict__ gate_fn_W,
                       const float* __restrict__ merge_W, const float* __restrict__ merge_b,
                       const float* __restrict__ attn_l, const float* __restrict__ attn_r) {
    int idx = blockIdx.x * blockDim.x + threadIdx.x;
    if (idx < Nn) g_deg[idx] = 0;
    if (idx < KIN * NC) {
        int k = idx / NC, j = idx % NC;
        float v = 0.f;
        if (j < 256)      v = W_gat[k * 256 + j];
        else if (j < 320) v = gate_m_W[k * 64 + (j - 256)];
        else if (j < 324) v = gate_fn_W[k * 4 + (j - 320)];            // q: x part of gate
        else if (j < 328) v = gate_fn_W[(320 + k) * 4 + (j - 324)];    // p: mean_z part projected
        else if (j < 392) v = merge_W[k * 64 + (j - 328)];             // merge x-part
        else if (j < 396) {                                             // el fold
            int h = j - 392; float s = 0.f;
            for (int o = 0; o < 64; o++) s = fmaf(W_gat[k * 256 + h * 64 + o], attn_l[h * 64 + o], s);
            v = s;
        } else if (j < 400) {                                           // er fold
            int h = j - 396; float s = 0.f;
            for (int o = 0; o < 64; o++) s = fmaf(W_gat[k * 256 + h * 64 + o], attn_r[h * 64 + o], s);
            v = s;
        }
        g_Wc[idx] = v;
    }
    if (idx < NC) {
        float b = 0.f;
        if (idx >= 256 && idx < 320)      b = gate_m_b[idx - 256];
        else if (idx >= 328 && idx < 392) b = merge_b[idx - 328];
        g_bias[idx] = b;
    }
}

// ---------------- CSR build ----------------
__global__ void k_deg(const int* __restrict__ dst) {
    int e = blockIdx.x * blockDim.x + threadIdx.x;
    if (e < Ee) atomicAdd(&g_deg[dst[e]], 1);
}

__global__ void k_scan() {  // single block, 1024 threads, warp-shuffle scan
    __shared__ int wsum[32];
    __shared__ int carry_s;
    int tid = threadIdx.x, lane = tid & 31, wid = tid >> 5;
    if (tid == 0) carry_s = 0;
    __syncthreads();
    for (int base = 0; base < Nn; base += 1024) {
        int i = base + tid;
        int v = (i < Nn) ? g_deg[i] : 0;
        int s = v;
#pragma unroll
        for (int off = 1; off < 32; off <<= 1) {
            int t = __shfl_up_sync(0xffffffffu, s, off);
            if (lane >= off) s += t;
        }
        if (lane == 31) wsum[wid] = s;
        __syncthreads();
        if (wid == 0) {
            int ws = wsum[lane];
#pragma unroll
            for (int off = 1; off < 32; off <<= 1) {
                int t = __shfl_up_sync(0xffffffffu, ws, off);
                if (lane >= off) ws += t;
            }
            wsum[lane] = ws;
        }
        __syncthreads();
        int excl = carry_s + (wid ? wsum[wid - 1] : 0) + s - v;
        if (i < Nn) { g_off[i] = excl; g_cur[i] = excl; }
        __syncthreads();
        if (tid == 0) carry_s += wsum[31];
        __syncthreads();
    }
    if (tid == 0) g_off[Nn] = carry_s;
}

__global__ void k_fill(const int* __restrict__ src, const int* __restrict__ dst) {
    int e = blockIdx.x * blockDim.x + threadIdx.x;
    if (e < Ee) {
        int pos = atomicAdd(&g_cur[dst[e]], 1);
        g_csr[pos] = src[e];
    }
}

// ---------------- fused GEMM: g_lin = x @ Wc + bias  (M=50000, K=256, N=448) -----
// 128x64 tile, KT=16, f32x2 packed FMA (2 FMAs/inst on fma pipe)
#define KT 16
__global__ __launch_bounds__(256) void k_gemm(const float* __restrict__ x) {
    __shared__ float As[KT][128];
    __shared__ float Bs[KT][64];
    const int bCol = blockIdx.x * 64;
    const int bRow = blockIdx.y * 128;
    const int tid = threadIdx.x;
    const int tr = tid >> 4;    // 0..15 row group (8 rows)
    const int tc = tid & 15;    // 0..15 col group (4 cols)

    unsigned long long acc2[4][4];   // [row-pair][col]
#pragma unroll
    for (int p = 0; p < 4; p++)
#pragma unroll
        for (int j = 0; j < 4; j++) acc2[p][j] = 0ull;

    const int amRow = tid >> 1;        // 0..127
    const int ak = (tid & 1) * 8;      // 0 or 8
    const int bk = tid >> 4;           // 0..15
    const int nb = (tid & 15) * 4;     // 0..60
    const int gmA = bRow + amRow;
    const float* xrow = x + (long long)gmA * KIN;

    for (int k0 = 0; k0 < KIN; k0 += KT) {
        float4 a0 = make_float4(0.f, 0.f, 0.f, 0.f), a1 = a0;
        if (gmA < Nn) {
            a0 = *reinterpret_cast<const float4*>(xrow + k0 + ak);
            a1 = *reinterpret_cast<const float4*>(xrow + k0 + ak + 4);
        }
        As[ak + 0][amRow] = a0.x; As[ak + 1][amRow] = a0.y;
        As[ak + 2][amRow] = a0.z; As[ak + 3][amRow] = a0.w;
        As[ak + 4][amRow] = a1.x; As[ak + 5][amRow] = a1.y;
        As[ak + 6][amRow] = a1.z; As[ak + 7][amRow] = a1.w;
        float4 bv = *reinterpret_cast<const float4*>(&g_Wc[(k0 + bk) * NC + bCol + nb]);
        *reinterpret_cast<float4*>(&Bs[bk][nb]) = bv;
        __syncthreads();
#pragma unroll
        for (int kk = 0; kk < KT; kk++) {
            ulonglong2 ap01 = *reinterpret_cast<const ulonglong2*>(&As[kk][tr * 8]);
            ulonglong2 ap23 = *reinterpret_cast<const ulonglong2*>(&As[kk][tr * 8 + 4]);
            float4 bq = *reinterpret_cast<const float4*>(&Bs[kk][tc * 4]);
            unsigned long long ap[4] = {ap01.x, ap01.y, ap23.x, ap23.y};
            unsigned long long bd[4] = {dupf(bq.x), dupf(bq.y), dupf(bq.z), dupf(bq.w)};
#pragma unroll
            for (int p = 0; p < 4; p++)
#pragma unroll
                for (int j = 0; j < 4; j++) fma2(acc2[p][j], ap[p], bd[j]);
        }
        __syncthreads();
    }

    const int gc = bCol + tc * 4;
    float4 bias = *reinterpret_cast<const float4*>(&g_bias[gc]);
#pragma unroll
    for (int p = 0; p < 4; p++) {
        float2 c0 = unpack2(acc2[p][0]);
        float2 c1 = unpack2(acc2[p][1]);
        float2 c2 = unpack2(acc2[p][2]);
        float2 c3 = unpack2(acc2[p][3]);
        int gm0 = bRow + tr * 8 + 2 * p;
        if (gm0 < Nn) {
            float4 v = make_float4(c0.x + bias.x, c1.x + bias.y, c2.x + bias.z, c3.x + bias.w);
            *reinterpret_cast<float4*>(&g_lin[(long long)gm0 * NC + gc]) = v;
        }
        if (gm0 + 1 < Nn) {
            float4 v = make_float4(c0.y + bias.x, c1.y + bias.y, c2.y + bias.z, c3.y + bias.w);
            *reinterpret_cast<float4*>(&g_lin[(long long)(gm0 + 1) * NC + gc]) = v;
        }
    }
}

// ---------------- single-pass aggregation: warp per node -------------------------
__global__ __launch_bounds__(256) void k_aggr(const float* __restrict__ gate_fn_W,
                                              const float* __restrict__ gate_fn_b,
                                              const float* __restrict__ merge_W,
                                              float* __restrict__ out) {
    __shared__ float sW2[64][64];   // merge_W rows 256..319
    __shared__ float sGm[64][4];    // gate_fn_W rows 256..319 (max_z part)
    __shared__ float sGated[8][64];
    int tid = threadIdx.x;
    for (int i = tid; i < 64 * 64; i += 256) ((float*)sW2)[i] = merge_W[256 * 64 + i];
    for (int i = tid; i < 64 * 4; i += 256) ((float*)sGm)[i] = gate_fn_W[256 * 4 + i];
    __syncthreads();

    int warp = tid >> 5, lane = tid & 31;
    int n = blockIdx.x * 8 + warp;
    if (n >= Nn) return;

    int start = g_off[n], end = g_off[n + 1];
    int deg = end - start;
    int lh = lane & 3;
    const float* row_n = &g_lin[(long long)n * NC];
    float er_h = row_n[396 + lh];

    float zc0 = -INFINITY, zc1 = -INFINITY;
    float psum = 0.f, ssum = 0.f;
    float acc[8] = {0.f, 0.f, 0.f, 0.f, 0.f, 0.f, 0.f, 0.f};

    // ---- ONE pass over in-edges ----
    for (int i = start; i < end; i++) {
        int s = g_csr[i];
        const float* row = &g_lin[(long long)s * NC];
        zc0 = fmaxf(zc0, row[256 + lane]);
        zc1 = fmaxf(zc1, row[288 + lane]);
        float e = row[392 + lh] + er_h;
        e = e > 0.f ? e : SLOPE * e;
        float w = __expf(e);        // no max-shift needed: |e| <= ~6
        ssum += w;
        psum += row[324 + lh];
        float a0 = __shfl_sync(0xffffffffu, w, 0);
        float a1 = __shfl_sync(0xffffffffu, w, 1);
        float a2 = __shfl_sync(0xffffffffu, w, 2);
        float a3 = __shfl_sync(0xffffffffu, w, 3);
        acc[0] = fmaf(a0, row[lane], acc[0]);
        acc[1] = fmaf(a0, row[lane + 32], acc[1]);
        acc[2] = fmaf(a1, row[lane + 64], acc[2]);
        acc[3] = fmaf(a1, row[lane + 96], acc[3]);
        acc[4] = fmaf(a2, row[lane + 128], acc[4]);
        acc[5] = fmaf(a2, row[lane + 160], acc[5]);
        acc[6] = fmaf(a3, row[lane + 192], acc[6]);
        acc[7] = fmaf(a3, row[lane + 224], acc[7]);
    }
    if (deg == 0) { zc0 = 0.f; zc1 = 0.f; }

    // ---- gate: sigmoid(q + zmax@Wm + psum/deg + b), fused with softmax 1/ssum ----
    float red[4];
#pragma unroll
    for (int h = 0; h < 4; h++) red[h] = zc0 * sGm[lane][h] + zc1 * sGm[lane + 32][h];
#pragma unroll
    for (int h = 0; h < 4; h++) {
#pragma unroll
        for (int o = 16; o > 0; o >>= 1) red[h] += __shfl_xor_sync(0xffffffffu, red[h], o);
    }
    float red_h = (lh == 0) ? red[0] : (lh == 1) ? red[1] : (lh == 2) ? red[2] : red[3];
    float q_h = row_n[320 + lh];
    float rdeg = 1.0f / (float)max(deg, 1);
    float pre = q_h + red_h + psum * rdeg + gate_fn_b[lh];
    float gate = 1.0f / (1.0f + __expf(-pre));
    float rcp = 1.0f / fmaxf(ssum, 1e-16f);   // each lane iterated ALL edges -> full sum for its lh
    float coef = 0.25f * gate * rcp;
    float c0 = __shfl_sync(0xffffffffu, coef, 0);
    float c1 = __shfl_sync(0xffffffffu, coef, 1);
    float c2 = __shfl_sync(0xffffffffu, coef, 2);
    float c3 = __shfl_sync(0xffffffffu, coef, 3);

    sGated[warp][lane]      = c0 * acc[0] + c1 * acc[2] + c2 * acc[4] + c3 * acc[6];
    sGated[warp][lane + 32] = c0 * acc[1] + c1 * acc[3] + c2 * acc[5] + c3 * acc[7];
    __syncwarp();

    // ---- merge: out = merge_x(+b) + gated @ W2 ----
    float o0 = row_n[328 + lane];
    float o1 = row_n[328 + 32 + lane];
#pragma unroll
    for (int op = 0; op < 64; op++) {
        float gv = sGated[warp][op];
        o0 = fmaf(gv, sW2[op][lane], o0);
        o1 = fmaf(gv, sW2[op][lane + 32], o1);
    }
    out[n * 64 + lane] = o0;
    out[n * 64 + 32 + lane] = o1;
}

// ---------------- launch ----------------
extern "C" void kernel_launch(void* const* d_in, const int* in_sizes, int n_in,
                              void* d_out, int out_size) {
    const float* x         = (const float*)d_in[0];
    const int*   src       = (const int*)d_in[1];
    const int*   dst       = (const int*)d_in[2];
    const float* W_gat     = (const float*)d_in[3];
    const float* attn_l    = (const float*)d_in[4];
    const float* attn_r    = (const float*)d_in[5];
    const float* gate_m_W  = (const float*)d_in[6];
    const float* gate_m_b  = (const float*)d_in[7];
    const float* gate_fn_W = (const float*)d_in[8];
    const float* gate_fn_b = (const float*)d_in[9];
    const float* merge_W   = (const float*)d_in[10];
    const float* merge_b   = (const float*)d_in[11];
    float* out = (float*)d_out;

    k_prep<<<(KIN * NC + 255) / 256, 256>>>(W_gat, gate_m_W, gate_m_b, gate_fn_W,
                                            merge_W, merge_b, attn_l, attn_r);
    k_deg<<<(Ee + 255) / 256, 256>>>(dst);
    k_scan<<<1, 1024>>>();
    k_fill<<<(Ee + 255) / 256, 256>>>(src, dst);
    dim3 ggrid(NC / 64, (Nn + 127) / 128);
    k_gemm<<<ggrid, 256>>>(x);
    k_aggr<<<(Nn + 7) / 8, 256>>>(gate_fn_W, gate_fn_b, merge_W, out);
}

// round 4
// speedup vs baseline: 1.5677x; 1.2587x over previous
#include <cuda_runtime.h>
#include <cuda_bf16.h>
#include <cstdint>
#include <math.h>

#define Nn 50000
#define Ee 800000
#define KIN 256
#define NC 448   // 0:256 feat | 256:320 z | 320:324 q | 324:328 p | 328:392 merge_x | 392:396 el | 396:400 er | 400:448 pad
#define SLOPE 0.2f
#define STA 40   // smem row stride (bf16 elems) for ldmatrix tiles

// ---------------- scratch (device globals; no allocation allowed) ----------------
__device__ float g_lin[Nn * NC];
__device__ float g_Wc[KIN * NC];
__device__ float g_bias[NC];
__device__ unsigned short g_Wbh[NC * KIN];   // B operand [n][k] bf16 hi
__device__ unsigned short g_Wbl[NC * KIN];   // B operand [n][k] bf16 lo
__device__ unsigned short g_xh[Nn * KIN];    // A operand [m][k] bf16 hi
__device__ unsigned short g_xl[Nn * KIN];    // A operand [m][k] bf16 lo
__device__ int   g_deg[Nn];
__device__ int   g_off[Nn + 1];
__device__ int   g_cur[Nn];
__device__ int   g_csr[Ee];

// ---------------- PTX helpers (all sm_80-baseline, no 'a' features) ----------------
__device__ __forceinline__ uint32_t smem_u32(const void* p) {
    uint32_t a;
    asm("{ .reg .u64 t; cvta.to.shared.u64 t, %1; cvt.u32.u64 %0, t; }" : "=r"(a) : "l"(p));
    return a;
}
__device__ __forceinline__ void ldsm_x4(uint32_t* r, uint32_t addr) {
    asm volatile("ldmatrix.sync.aligned.m8n8.x4.shared.b16 {%0,%1,%2,%3}, [%4];"
                 : "=r"(r[0]), "=r"(r[1]), "=r"(r[2]), "=r"(r[3]) : "r"(addr));
}
__device__ __forceinline__ void mma16816(float* c, const uint32_t* a, const uint32_t* b) {
    asm volatile("mma.sync.aligned.m16n8k16.row.col.f32.bf16.bf16.f32 "
                 "{%0,%1,%2,%3}, {%4,%5,%6,%7}, {%8,%9}, {%0,%1,%2,%3};"
                 : "+f"(c[0]), "+f"(c[1]), "+f"(c[2]), "+f"(c[3])
                 : "r"(a[0]), "r"(a[1]), "r"(a[2]), "r"(a[3]), "r"(b[0]), "r"(b[1]));
}

// ---------------- weight prep: combined [256 x 448] weight + bias + deg zero -----
__global__ void k_prep(const float* __restrict__ W_gat, const float* __restrict__ gate_m_W,
                       const float* __restrict__ gate_m_b, const float* __restrict__ gate_fn_W,
                       const float* __restrict__ merge_W, const float* __restrict__ merge_b,
                       const float* __restrict__ attn_l, const float* __restrict__ attn_r) {
    int idx = blockIdx.x * blockDim.x + threadIdx.x;
    if (idx < Nn) g_deg[idx] = 0;
    if (idx < KIN * NC) {
        int k = idx / NC, j = idx % NC;
        float v = 0.f;
        if (j < 256)      v = W_gat[k * 256 + j];
        else if (j < 320) v = gate_m_W[k * 64 + (j - 256)];
        else if (j < 324) v = gate_fn_W[k * 4 + (j - 320)];
        else if (j < 328) v = gate_fn_W[(320 + k) * 4 + (j - 324)];
        else if (j < 392) v = merge_W[k * 64 + (j - 328)];
        else if (j < 396) {
            int h = j - 392; float s = 0.f;
            for (int o = 0; o < 64; o++) s = fmaf(W_gat[k * 256 + h * 64 + o], attn_l[h * 64 + o], s);
            v = s;
        } else if (j < 400) {
            int h = j - 396; float s = 0.f;
            for (int o = 0; o < 64; o++) s = fmaf(W_gat[k * 256 + h * 64 + o], attn_r[h * 64 + o], s);
            v = s;
        }
        g_Wc[idx] = v;
    }
    if (idx < NC) {
        float b = 0.f;
        if (idx >= 256 && idx < 320)      b = gate_m_b[idx - 256];
        else if (idx >= 328 && idx < 392) b = merge_b[idx - 328];
        g_bias[idx] = b;
    }
}

// ---------------- transpose+split Wc into bf16 hi/lo B operand [n][k] ----------
__global__ void k_prep2() {
    int idx = blockIdx.x * blockDim.x + threadIdx.x;
    if (idx >= NC * KIN) return;
    int n = idx / KIN, k = idx % KIN;
    float v = g_Wc[k * NC + n];
    __nv_bfloat16 h = __float2bfloat16(v);
    __nv_bfloat16 l = __float2bfloat16(v - __bfloat162float(h));
    g_Wbh[idx] = __bfloat16_as_ushort(h);
    g_Wbl[idx] = __bfloat16_as_ushort(l);
}

// ---------------- split x into bf16 hi/lo (vectorized) ----------
__global__ void k_split(const float* __restrict__ x) {
    int i = blockIdx.x * blockDim.x + threadIdx.x;     // float4 granularity
    if (i >= Nn * KIN / 4) return;
    float4 v = reinterpret_cast<const float4*>(x)[i];
    float f[4] = {v.x, v.y, v.z, v.w};
    unsigned short hs[4], ls[4];
#pragma unroll
    for (int j = 0; j < 4; j++) {
        __nv_bfloat16 h = __float2bfloat16(f[j]);
        __nv_bfloat16 l = __float2bfloat16(f[j] - __bfloat162float(h));
        hs[j] = __bfloat16_as_ushort(h);
        ls[j] = __bfloat16_as_ushort(l);
    }
    reinterpret_cast<ushort4*>(g_xh)[i] = *reinterpret_cast<ushort4*>(hs);
    reinterpret_cast<ushort4*>(g_xl)[i] = *reinterpret_cast<ushort4*>(ls);
}

// ---------------- CSR build ----------------
__global__ void k_deg(const int* __restrict__ dst) {
    int e = blockIdx.x * blockDim.x + threadIdx.x;
    if (e < Ee) atomicAdd(&g_deg[dst[e]], 1);
}

__global__ void k_scan() {
    __shared__ int wsum[32];
    __shared__ int carry_s;
    int tid = threadIdx.x, lane = tid & 31, wid = tid >> 5;
    if (tid == 0) carry_s = 0;
    __syncthreads();
    for (int base = 0; base < Nn; base += 1024) {
        int i = base + tid;
        int v = (i < Nn) ? g_deg[i] : 0;
        int s = v;
#pragma unroll
        for (int off = 1; off < 32; off <<= 1) {
            int t = __shfl_up_sync(0xffffffffu, s, off);
            if (lane >= off) s += t;
        }
        if (lane == 31) wsum[wid] = s;
        __syncthreads();
        if (wid == 0) {
            int ws = wsum[lane];
#pragma unroll
            for (int off = 1; off < 32; off <<= 1) {
                int t = __shfl_up_sync(0xffffffffu, ws, off);
                if (lane >= off) ws += t;
            }
            wsum[lane] = ws;
        }
        __syncthreads();
        int excl = carry_s + (wid ? wsum[wid - 1] : 0) + s - v;
        if (i < Nn) { g_off[i] = excl; g_cur[i] = excl; }
        __syncthreads();
        if (tid == 0) carry_s += wsum[31];
        __syncthreads();
    }
    if (tid == 0) g_off[Nn] = carry_s;
}

__global__ void k_fill(const int* __restrict__ src, const int* __restrict__ dst) {
    int e = blockIdx.x * blockDim.x + threadIdx.x;
    if (e < Ee) {
        int pos = atomicAdd(&g_cur[dst[e]], 1);
        g_csr[pos] = src[e];
    }
}

// ---------------- HMMA GEMM: g_lin = x @ Wc + bias via mma.sync bf16 3-term -----
// CTA tile M=128, N=64; 8 warps as 4(M)x2(N), warp tile 32x32. K chunks of 32.
__global__ __launch_bounds__(256) void k_gemm_mma(const float* __restrict__ dummy) {
    __shared__ __align__(16) unsigned short sAh[128 * STA];
    __shared__ __align__(16) unsigned short sAl[128 * STA];
    __shared__ __align__(16) unsigned short sBh[64 * STA];
    __shared__ __align__(16) unsigned short sBl[64 * STA];

    const int tid = threadIdx.x;
    const int wid = tid >> 5, lane = tid & 31;
    const int wm = wid & 3, wn = wid >> 2;        // warp coords: 4 x 2
    const int bRow = blockIdx.y * 128;
    const int bCol = blockIdx.x * 64;

    float acc[2][4][4];
#pragma unroll
    for (int mt = 0; mt < 2; mt++)
#pragma unroll
        for (int nt = 0; nt < 4; nt++)
#pragma unroll
            for (int j = 0; j < 4; j++) acc[mt][nt][j] = 0.f;

    // per-thread load coords
    const int arow = tid >> 2;            // 0..63
    const int akc = (tid & 3) * 8;        // 0,8,16,24

    // ldmatrix frag addresses (constant across chunks except ks offset)
    const int aRowF = wm * 32 + (lane & 15);
    const int aKF = (lane >> 4) * 8;
    const int bRowF = wn * 32 + (lane & 7) + ((lane >> 4) & 1) * 8;
    const int bKF = ((lane >> 3) & 1) * 8;

    for (int kc = 0; kc < KIN; kc += 32) {
        // ---- stage A (128x32 hi+lo) ----
#pragma unroll
        for (int it = 0; it < 2; it++) {
            int row = arow + it * 64;
            int gm = bRow + row;
            uint4 vh = make_uint4(0, 0, 0, 0), vl = vh;
            if (gm < Nn) {
                vh = *reinterpret_cast<const uint4*>(&g_xh[(size_t)gm * KIN + kc + akc]);
                vl = *reinterpret_cast<const uint4*>(&g_xl[(size_t)gm * KIN + kc + akc]);
            }
            *reinterpret_cast<uint4*>(&sAh[row * STA + akc]) = vh;
            *reinterpret_cast<uint4*>(&sAl[row * STA + akc]) = vl;
        }
        // ---- stage B (64x32 hi+lo) ----
        {
            int gn = bCol + arow;
            uint4 wh = *reinterpret_cast<const uint4*>(&g_Wbh[(size_t)gn * KIN + kc + akc]);
            uint4 wl = *reinterpret_cast<const uint4*>(&g_Wbl[(size_t)gn * KIN + kc + akc]);
            *reinterpret_cast<uint4*>(&sBh[arow * STA + akc]) = wh;
            *reinterpret_cast<uint4*>(&sBl[arow * STA + akc]) = wl;
        }
        __syncthreads();

#pragma unroll
        for (int ks = 0; ks < 2; ks++) {
            uint32_t ah[2][4], al[2][4];
#pragma unroll
            for (int mt = 0; mt < 2; mt++) {
                uint32_t addr = smem_u32(&sAh[(aRowF + mt * 16) * STA + ks * 16 + aKF]);
                ldsm_x4(ah[mt], addr);
                addr = smem_u32(&sAl[(aRowF + mt * 16) * STA + ks * 16 + aKF]);
                ldsm_x4(al[mt], addr);
            }
            uint32_t bh[2][4], bl[2][4];   // [pair of n8 tiles][regs]
#pragma unroll
            for (int p = 0; p < 2; p++) {
                uint32_t addr = smem_u32(&sBh[(bRowF + p * 16) * STA + ks * 16 + bKF]);
                ldsm_x4(bh[p], addr);
                addr = smem_u32(&sBl[(bRowF + p * 16) * STA + ks * 16 + bKF]);
                ldsm_x4(bl[p], addr);
            }
#pragma unroll
            for (int mt = 0; mt < 2; mt++) {
#pragma unroll
                for (int nt = 0; nt < 4; nt++) {
                    const uint32_t* bhf = &bh[nt >> 1][(nt & 1) * 2];
                    const uint32_t* blf = &bl[nt >> 1][(nt & 1) * 2];
                    mma16816(acc[mt][nt], ah[mt], bhf);   // hi*hi
                    mma16816(acc[mt][nt], al[mt], bhf);   // lo*hi
                    mma16816(acc[mt][nt], ah[mt], blf);   // hi*lo
                }
            }
        }
        __syncthreads();
    }

    // ---- epilogue: accumulators -> g_lin (+bias) ----
#pragma unroll
    for (int mt = 0; mt < 2; mt++) {
#pragma unroll
        for (int nt = 0; nt < 4; nt++) {
            int r0 = bRow + wm * 32 + mt * 16 + (lane >> 2);
            int c0 = bCol + wn * 32 + nt * 8 + 2 * (lane & 3);
            float b0 = g_bias[c0], b1 = g_bias[c0 + 1];
            if (r0 < Nn) {
                float2 v = make_float2(acc[mt][nt][0] + b0, acc[mt][nt][1] + b1);
                *reinterpret_cast<float2*>(&g_lin[(size_t)r0 * NC + c0]) = v;
            }
            if (r0 + 8 < Nn) {
                float2 v = make_float2(acc[mt][nt][2] + b0, acc[mt][nt][3] + b1);
                *reinterpret_cast<float2*>(&g_lin[(size_t)(r0 + 8) * NC + c0]) = v;
            }
        }
    }
}

// ---------------- single-pass aggregation: warp per node -------------------------
__global__ __launch_bounds__(256) void k_aggr(const float* __restrict__ gate_fn_W,
                                              const float* __restrict__ gate_fn_b,
                                              const float* __restrict__ merge_W,
                                              float* __restrict__ out) {
    __shared__ float sW2[64][64];
    __shared__ float sGm[64][4];
    __shared__ float sGated[8][64];
    int tid = threadIdx.x;
    for (int i = tid; i < 64 * 64; i += 256) ((float*)sW2)[i] = merge_W[256 * 64 + i];
    for (int i = tid; i < 64 * 4; i += 256) ((float*)sGm)[i] = gate_fn_W[256 * 4 + i];
    __syncthreads();

    int warp = tid >> 5, lane = tid & 31;
    int n = blockIdx.x * 8 + warp;
    if (n >= Nn) return;

    int start = g_off[n], end = g_off[n + 1];
    int deg = end - start;
    int lh = lane & 3;
    const float* row_n = &g_lin[(size_t)n * NC];
    float er_h = row_n[396 + lh];

    float zc0 = -INFINITY, zc1 = -INFINITY;
    float psum = 0.f, ssum = 0.f;
    float acc[8] = {0.f, 0.f, 0.f, 0.f, 0.f, 0.f, 0.f, 0.f};

    for (int i = start; i < end; i++) {
        int s = g_csr[i];
        const float* row = &g_lin[(size_t)s * NC];
        zc0 = fmaxf(zc0, row[256 + lane]);
        zc1 = fmaxf(zc1, row[288 + lane]);
        float e = row[392 + lh] + er_h;
        e = e > 0.f ? e : SLOPE * e;
        float w = __expf(e);
        ssum += w;
        psum += row[324 + lh];
        float a0 = __shfl_sync(0xffffffffu, w, 0);
        float a1 = __shfl_sync(0xffffffffu, w, 1);
        float a2 = __shfl_sync(0xffffffffu, w, 2);
        float a3 = __shfl_sync(0xffffffffu, w, 3);
        acc[0] = fmaf(a0, row[lane], acc[0]);
        acc[1] = fmaf(a0, row[lane + 32], acc[1]);
        acc[2] = fmaf(a1, row[lane + 64], acc[2]);
        acc[3] = fmaf(a1, row[lane + 96], acc[3]);
        acc[4] = fmaf(a2, row[lane + 128], acc[4]);
        acc[5] = fmaf(a2, row[lane + 160], acc[5]);
        acc[6] = fmaf(a3, row[lane + 192], acc[6]);
        acc[7] = fmaf(a3, row[lane + 224], acc[7]);
    }
    if (deg == 0) { zc0 = 0.f; zc1 = 0.f; }

    float red[4];
#pragma unroll
    for (int h = 0; h < 4; h++) red[h] = zc0 * sGm[lane][h] + zc1 * sGm[lane + 32][h];
#pragma unroll
    for (int h = 0; h < 4; h++) {
#pragma unroll
        for (int o = 16; o > 0; o >>= 1) red[h] += __shfl_xor_sync(0xffffffffu, red[h], o);
    }
    float red_h = (lh == 0) ? red[0] : (lh == 1) ? red[1] : (lh == 2) ? red[2] : red[3];
    float q_h = row_n[320 + lh];
    float rdeg = 1.0f / (float)max(deg, 1);
    float pre = q_h + red_h + psum * rdeg + gate_fn_b[lh];
    float gate = 1.0f / (1.0f + __expf(-pre));
    float rcp = 1.0f / fmaxf(ssum, 1e-16f);
    float coef = 0.25f * gate * rcp;
    float c0 = __shfl_sync(0xffffffffu, coef, 0);
    float c1 = __shfl_sync(0xffffffffu, coef, 1);
    float c2 = __shfl_sync(0xffffffffu, coef, 2);
    float c3 = __shfl_sync(0xffffffffu, coef, 3);

    sGated[warp][lane]      = c0 * acc[0] + c1 * acc[2] + c2 * acc[4] + c3 * acc[6];
    sGated[warp][lane + 32] = c0 * acc[1] + c1 * acc[3] + c2 * acc[5] + c3 * acc[7];
    __syncwarp();

    float o0 = row_n[328 + lane];
    float o1 = row_n[328 + 32 + lane];
#pragma unroll
    for (int op = 0; op < 64; op++) {
        float gv = sGated[warp][op];
        o0 = fmaf(gv, sW2[op][lane], o0);
        o1 = fmaf(gv, sW2[op][lane + 32], o1);
    }
    out[n * 64 + lane] = o0;
    out[n * 64 + 32 + lane] = o1;
}

// ---------------- launch ----------------
extern "C" void kernel_launch(void* const* d_in, const int* in_sizes, int n_in,
                              void* d_out, int out_size) {
    const float* x         = (const float*)d_in[0];
    const int*   src       = (const int*)d_in[1];
    const int*   dst       = (const int*)d_in[2];
    const float* W_gat     = (const float*)d_in[3];
    const float* attn_l    = (const float*)d_in[4];
    const float* attn_r    = (const float*)d_in[5];
    const float* gate_m_W  = (const float*)d_in[6];
    const float* gate_m_b  = (const float*)d_in[7];
    const float* gate_fn_W = (const float*)d_in[8];
    const float* gate_fn_b = (const float*)d_in[9];
    const float* merge_W   = (const float*)d_in[10];
    const float* merge_b   = (const float*)d_in[11];
    float* out = (float*)d_out;

    k_prep<<<(KIN * NC + 255) / 256, 256>>>(W_gat, gate_m_W, gate_m_b, gate_fn_W,
                                            merge_W, merge_b, attn_l, attn_r);
    k_prep2<<<(NC * KIN + 255) / 256, 256>>>();
    k_split<<<(Nn * KIN / 4 + 255) / 256, 256>>>(x);
    k_deg<<<(Ee + 255) / 256, 256>>>(dst);
    k_scan<<<1, 1024>>>();
    k_fill<<<(Ee + 255) / 256, 256>>>(src, dst);
    dim3 ggrid(NC / 64, (Nn + 127) / 128);
    k_gemm_mma<<<ggrid, 256>>>(x);
    k_aggr<<<(Nn + 7) / 8, 256>>>(gate_fn_W, gate_fn_b, merge_W, out);
}

// round 5
// speedup vs baseline: 1.7356x; 1.1071x over previous
#include <cuda_runtime.h>
#include <cuda_bf16.h>
#include <cuda_fp16.h>
#include <cstdint>
#include <math.h>

#define Nn 50000
#define Ee 800000
#define KIN 256
#define NC 448   // 0:256 feat | 256:320 z | 320:384 merge_x | 384:388 q | 388:392 p | 392:396 el | 396:400 er | 400:448 pad
#define SLOPE 0.2f
#define STA 40   // smem row stride (bf16 elems) for ldmatrix tiles

// ---------------- scratch (device globals; no allocation allowed) ----------------
__device__ float g_Wc[KIN * NC];
__device__ float g_bias[NC];
__device__ unsigned short g_Wbh[NC * KIN];   // B operand [n][k] bf16 hi
__device__ unsigned short g_Wbl[NC * KIN];   // B operand [n][k] bf16 lo
__device__ unsigned short g_xh[Nn * KIN];    // A operand [m][k] bf16 hi
__device__ unsigned short g_xl[Nn * KIN];    // A operand [m][k] bf16 lo
__device__ __half2 g_fH[Nn * 128];           // feat fp16 [m][128 half2]
__device__ __half2 g_zH[Nn * 32];            // z fp16 [m][32 half2]
__device__ float   g_mx[Nn * 64];            // merge_x fp32
__device__ float   g_misc[Nn * 16];          // q(0-3) p(4-7) el(8-11) er(12-15)
__device__ int   g_deg[Nn];
__device__ int   g_off[Nn + 1];
__device__ int   g_cur[Nn];
__device__ int   g_csr[Ee];

// ---------------- PTX helpers (sm_80-baseline) ----------------
__device__ __forceinline__ uint32_t smem_u32(const void* p) {
    uint32_t a;
    asm("{ .reg .u64 t; cvta.to.shared.u64 t, %1; cvt.u32.u64 %0, t; }" : "=r"(a) : "l"(p));
    return a;
}
__device__ __forceinline__ void ldsm_x4(uint32_t* r, uint32_t addr) {
    asm volatile("ldmatrix.sync.aligned.m8n8.x4.shared.b16 {%0,%1,%2,%3}, [%4];"
                 : "=r"(r[0]), "=r"(r[1]), "=r"(r[2]), "=r"(r[3]) : "r"(addr));
}
__device__ __forceinline__ void mma16816(float* c, const uint32_t* a, const uint32_t* b) {
    asm volatile("mma.sync.aligned.m16n8k16.row.col.f32.bf16.bf16.f32 "
                 "{%0,%1,%2,%3}, {%4,%5,%6,%7}, {%8,%9}, {%0,%1,%2,%3};"
                 : "+f"(c[0]), "+f"(c[1]), "+f"(c[2]), "+f"(c[3])
                 : "r"(a[0]), "r"(a[1]), "r"(a[2]), "r"(a[3]), "r"(b[0]), "r"(b[1]));
}

// ---------------- weight prep ----------------
__global__ void k_prep(const float* __restrict__ W_gat, const float* __restrict__ gate_m_W,
                       const float* __restrict__ gate_m_b, const float* __restrict__ gate_fn_W,
                       const float* __restrict__ merge_W, const float* __restrict__ merge_b,
                       const float* __restrict__ attn_l, const float* __restrict__ attn_r) {
    int idx = blockIdx.x * blockDim.x + threadIdx.x;
    if (idx < Nn) g_deg[idx] = 0;
    if (idx < KIN * NC) {
        int k = idx / NC, j = idx % NC;
        float v = 0.f;
        if (j < 256)      v = W_gat[k * 256 + j];
        else if (j < 320) v = gate_m_W[k * 64 + (j - 256)];
        else if (j < 384) v = merge_W[k * 64 + (j - 320)];
        else if (j < 388) v = gate_fn_W[k * 4 + (j - 384)];             // q
        else if (j < 392) v = gate_fn_W[(320 + k) * 4 + (j - 388)];     // p (mean_z projected)
        else if (j < 396) {                                              // el fold
            int h = j - 392; float s = 0.f;
            for (int o = 0; o < 64; o++) s = fmaf(W_gat[k * 256 + h * 64 + o], attn_l[h * 64 + o], s);
            v = s;
        } else if (j < 400) {                                            // er fold
            int h = j - 396; float s = 0.f;
            for (int o = 0; o < 64; o++) s = fmaf(W_gat[k * 256 + h * 64 + o], attn_r[h * 64 + o], s);
            v = s;
        }
        g_Wc[idx] = v;
    }
    if (idx < NC) {
        float b = 0.f;
        if (idx >= 256 && idx < 320)      b = gate_m_b[idx - 256];
        else if (idx >= 320 && idx < 384) b = merge_b[idx - 320];
        g_bias[idx] = b;
    }
}

// ---------------- transpose+split Wc into bf16 hi/lo B operand [n][k] ----------
__global__ void k_prep2() {
    int idx = blockIdx.x * blockDim.x + threadIdx.x;
    if (idx >= NC * KIN) return;
    int n = idx / KIN, k = idx % KIN;
    float v = g_Wc[k * NC + n];
    __nv_bfloat16 h = __float2bfloat16(v);
    __nv_bfloat16 l = __float2bfloat16(v - __bfloat162float(h));
    g_Wbh[idx] = __bfloat16_as_ushort(h);
    g_Wbl[idx] = __bfloat16_as_ushort(l);
}

// ---------------- split x into bf16 hi/lo ----------
__global__ void k_split(const float* __restrict__ x) {
    int i = blockIdx.x * blockDim.x + threadIdx.x;
    if (i >= Nn * KIN / 4) return;
    float4 v = reinterpret_cast<const float4*>(x)[i];
    float f[4] = {v.x, v.y, v.z, v.w};
    unsigned short hs[4], ls[4];
#pragma unroll
    for (int j = 0; j < 4; j++) {
        __nv_bfloat16 h = __float2bfloat16(f[j]);
        __nv_bfloat16 l = __float2bfloat16(f[j] - __bfloat162float(h));
        hs[j] = __bfloat16_as_ushort(h);
        ls[j] = __bfloat16_as_ushort(l);
    }
    reinterpret_cast<ushort4*>(g_xh)[i] = *reinterpret_cast<ushort4*>(hs);
    reinterpret_cast<ushort4*>(g_xl)[i] = *reinterpret_cast<ushort4*>(ls);
}

// ---------------- CSR build ----------------
__global__ void k_deg(const int* __restrict__ dst) {
    int e = blockIdx.x * blockDim.x + threadIdx.x;
    if (e < Ee) atomicAdd(&g_deg[dst[e]], 1);
}

__global__ void k_scan() {
    __shared__ int wsum[32];
    __shared__ int carry_s;
    int tid = threadIdx.x, lane = tid & 31, wid = tid >> 5;
    if (tid == 0) carry_s = 0;
    __syncthreads();
    for (int base = 0; base < Nn; base += 1024) {
        int i = base + tid;
        int v = (i < Nn) ? g_deg[i] : 0;
        int s = v;
#pragma unroll
        for (int off = 1; off < 32; off <<= 1) {
            int t = __shfl_up_sync(0xffffffffu, s, off);
            if (lane >= off) s += t;
        }
        if (lane == 31) wsum[wid] = s;
        __syncthreads();
        if (wid == 0) {
            int ws = wsum[lane];
#pragma unroll
            for (int off = 1; off < 32; off <<= 1) {
                int t = __shfl_up_sync(0xffffffffu, ws, off);
                if (lane >= off) ws += t;
            }
            wsum[lane] = ws;
        }
        __syncthreads();
        int excl = carry_s + (wid ? wsum[wid - 1] : 0) + s - v;
        if (i < Nn) { g_off[i] = excl; g_cur[i] = excl; }
        __syncthreads();
        if (tid == 0) carry_s += wsum[31];
        __syncthreads();
    }
    if (tid == 0) g_off[Nn] = carry_s;
}

__global__ void k_fill(const int* __restrict__ src, const int* __restrict__ dst) {
    int e = blockIdx.x * blockDim.x + threadIdx.x;
    if (e < Ee) {
        int pos = atomicAdd(&g_cur[dst[e]], 1);
        g_csr[pos] = src[e];
    }
}

// ---------------- HMMA GEMM, epilogue scatters to typed arrays -----
__global__ __launch_bounds__(256) void k_gemm_mma() {
    __shared__ __align__(16) unsigned short sAh[128 * STA];
    __shared__ __align__(16) unsigned short sAl[128 * STA];
    __shared__ __align__(16) unsigned short sBh[64 * STA];
    __shared__ __align__(16) unsigned short sBl[64 * STA];

    const int tid = threadIdx.x;
    const int wid = tid >> 5, lane = tid & 31;
    const int wm = wid & 3, wn = wid >> 2;
    const int bRow = blockIdx.y * 128;
    const int bCol = blockIdx.x * 64;

    float acc[2][4][4];
#pragma unroll
    for (int mt = 0; mt < 2; mt++)
#pragma unroll
        for (int nt = 0; nt < 4; nt++)
#pragma unroll
            for (int j = 0; j < 4; j++) acc[mt][nt][j] = 0.f;

    const int arow = tid >> 2;
    const int akc = (tid & 3) * 8;
    const int aRowF = wm * 32 + (lane & 15);
    const int aKF = (lane >> 4) * 8;
    const int bRowF = wn * 32 + (lane & 7) + ((lane >> 4) & 1) * 8;
    const int bKF = ((lane >> 3) & 1) * 8;

    for (int kc = 0; kc < KIN; kc += 32) {
#pragma unroll
        for (int it = 0; it < 2; it++) {
            int row = arow + it * 64;
            int gm = bRow + row;
            uint4 vh = make_uint4(0, 0, 0, 0), vl = vh;
            if (gm < Nn) {
                vh = *reinterpret_cast<const uint4*>(&g_xh[(size_t)gm * KIN + kc + akc]);
                vl = *reinterpret_cast<const uint4*>(&g_xl[(size_t)gm * KIN + kc + akc]);
            }
            *reinterpret_cast<uint4*>(&sAh[row * STA + akc]) = vh;
            *reinterpret_cast<uint4*>(&sAl[row * STA + akc]) = vl;
        }
        {
            int gn = bCol + arow;
            uint4 wh = *reinterpret_cast<const uint4*>(&g_Wbh[(size_t)gn * KIN + kc + akc]);
            uint4 wl = *reinterpret_cast<const uint4*>(&g_Wbl[(size_t)gn * KIN + kc + akc]);
            *reinterpret_cast<uint4*>(&sBh[arow * STA + akc]) = wh;
            *reinterpret_cast<uint4*>(&sBl[arow * STA + akc]) = wl;
        }
        __syncthreads();

#pragma unroll
        for (int ks = 0; ks < 2; ks++) {
            uint32_t ah[2][4], al[2][4];
#pragma unroll
            for (int mt = 0; mt < 2; mt++) {
                uint32_t addr = smem_u32(&sAh[(aRowF + mt * 16) * STA + ks * 16 + aKF]);
                ldsm_x4(ah[mt], addr);
                addr = smem_u32(&sAl[(aRowF + mt * 16) * STA + ks * 16 + aKF]);
                ldsm_x4(al[mt], addr);
            }
            uint32_t bh[2][4], bl[2][4];
#pragma unroll
            for (int p = 0; p < 2; p++) {
                uint32_t addr = smem_u32(&sBh[(bRowF + p * 16) * STA + ks * 16 + bKF]);
                ldsm_x4(bh[p], addr);
                addr = smem_u32(&sBl[(bRowF + p * 16) * STA + ks * 16 + bKF]);
                ldsm_x4(bl[p], addr);
            }
#pragma unroll
            for (int mt = 0; mt < 2; mt++) {
#pragma unroll
                for (int nt = 0; nt < 4; nt++) {
                    const uint32_t* bhf = &bh[nt >> 1][(nt & 1) * 2];
                    const uint32_t* blf = &bl[nt >> 1][(nt & 1) * 2];
                    mma16816(acc[mt][nt], ah[mt], bhf);
                    mma16816(acc[mt][nt], al[mt], bhf);
                    mma16816(acc[mt][nt], ah[mt], blf);
                }
            }
        }
        __syncthreads();
    }

    // ---- epilogue: scatter by section ----
#pragma unroll
    for (int mt = 0; mt < 2; mt++) {
#pragma unroll
        for (int nt = 0; nt < 4; nt++) {
            int r0 = bRow + wm * 32 + mt * 16 + (lane >> 2);
            int c0 = bCol + wn * 32 + nt * 8 + 2 * (lane & 3);
            float b0 = g_bias[c0], b1 = g_bias[c0 + 1];
            float2 v0 = make_float2(acc[mt][nt][0] + b0, acc[mt][nt][1] + b1);
            float2 v1 = make_float2(acc[mt][nt][2] + b0, acc[mt][nt][3] + b1);
#pragma unroll
            for (int rr = 0; rr < 2; rr++) {
                int r = r0 + rr * 8;
                float2 v = rr ? v1 : v0;
                if (r >= Nn) continue;
                if (bCol < 256) {
                    g_fH[(size_t)r * 128 + (c0 >> 1)] = __floats2half2_rn(v.x, v.y);
                } else if (bCol == 256) {
                    g_zH[(size_t)r * 32 + ((c0 - 256) >> 1)] = __floats2half2_rn(v.x, v.y);
                } else if (bCol == 320) {
                    *reinterpret_cast<float2*>(&g_mx[(size_t)r * 64 + (c0 - 320)]) = v;
                } else if (c0 < 400) {
                    *reinterpret_cast<float2*>(&g_misc[(size_t)r * 16 + (c0 - 384)]) = v;
                }
            }
        }
    }
}

// ---------------- single-pass aggregation: warp per node, fp16 gathers ------------
__global__ __launch_bounds__(256) void k_aggr(const float* __restrict__ gate_fn_W,
                                              const float* __restrict__ gate_fn_b,
                                              const float* __restrict__ merge_W,
                                              float* __restrict__ out) {
    __shared__ float sW2[64][64];
    __shared__ float sGm[64][4];
    __shared__ float sGated[8][64];
    int tid = threadIdx.x;
    for (int i = tid; i < 64 * 64; i += 256) ((float*)sW2)[i] = merge_W[256 * 64 + i];
    for (int i = tid; i < 64 * 4; i += 256) ((float*)sGm)[i] = gate_fn_W[256 * 4 + i];
    __syncthreads();

    int warp = tid >> 5, lane = tid & 31;
    int n = blockIdx.x * 8 + warp;
    if (n >= Nn) return;

    int start = g_off[n], end = g_off[n + 1];
    int deg = end - start;
    int lh = lane & 3;
    float er_h = g_misc[(size_t)n * 16 + 12 + lh];

    __half2 zmax = __halves2half2(__ushort_as_half(0xFC00), __ushort_as_half(0xFC00)); // -inf
    float psum = 0.f, ssum = 0.f;
    float2 acc[4];
#pragma unroll
    for (int k = 0; k < 4; k++) acc[k] = make_float2(0.f, 0.f);

    for (int i = start; i < end; i++) {
        int s = g_csr[i];
        zmax = __hmax2(zmax, g_zH[(size_t)s * 32 + lane]);
        const float* mrow = &g_misc[(size_t)s * 16];
        float e = mrow[8 + lh] + er_h;
        e = e > 0.f ? e : SLOPE * e;
        float w = __expf(e);
        ssum += w;
        psum += mrow[4 + lh];
        float a0 = __shfl_sync(0xffffffffu, w, 0);
        float a1 = __shfl_sync(0xffffffffu, w, 1);
        float a2 = __shfl_sync(0xffffffffu, w, 2);
        float a3 = __shfl_sync(0xffffffffu, w, 3);
        const __half2* fp = &g_fH[(size_t)s * 128];
        float2 f0 = __half22float2(fp[lane]);
        float2 f1 = __half22float2(fp[32 + lane]);
        float2 f2 = __half22float2(fp[64 + lane]);
        float2 f3 = __half22float2(fp[96 + lane]);
        acc[0].x = fmaf(a0, f0.x, acc[0].x); acc[0].y = fmaf(a0, f0.y, acc[0].y);
        acc[1].x = fmaf(a1, f1.x, acc[1].x); acc[1].y = fmaf(a1, f1.y, acc[1].y);
        acc[2].x = fmaf(a2, f2.x, acc[2].x); acc[2].y = fmaf(a2, f2.y, acc[2].y);
        acc[3].x = fmaf(a3, f3.x, acc[3].x); acc[3].y = fmaf(a3, f3.y, acc[3].y);
    }
    float2 zf;
    if (deg == 0) zf = make_float2(0.f, 0.f);
    else zf = __half22float2(zmax);

    // ---- gate: sigmoid(q + zmax@Wm + psum/deg + b) ----
    float red[4];
#pragma unroll
    for (int h = 0; h < 4; h++) red[h] = zf.x * sGm[2 * lane][h] + zf.y * sGm[2 * lane + 1][h];
#pragma unroll
    for (int h = 0; h < 4; h++) {
#pragma unroll
        for (int o = 16; o > 0; o >>= 1) red[h] += __shfl_xor_sync(0xffffffffu, red[h], o);
    }
    float red_h = (lh == 0) ? red[0] : (lh == 1) ? red[1] : (lh == 2) ? red[2] : red[3];
    float q_h = g_misc[(size_t)n * 16 + lh];
    float rdeg = 1.0f / (float)max(deg, 1);
    float pre = q_h + red_h + psum * rdeg + gate_fn_b[lh];
    float gate = 1.0f / (1.0f + __expf(-pre));
    float rcp = 1.0f / fmaxf(ssum, 1e-16f);
    float coef = 0.25f * gate * rcp;
    float c0 = __shfl_sync(0xffffffffu, coef, 0);
    float c1 = __shfl_sync(0xffffffffu, coef, 1);
    float c2 = __shfl_sync(0xffffffffu, coef, 2);
    float c3 = __shfl_sync(0xffffffffu, coef, 3);

    sGated[warp][2 * lane]     = c0 * acc[0].x + c1 * acc[1].x + c2 * acc[2].x + c3 * acc[3].x;
    sGated[warp][2 * lane + 1] = c0 * acc[0].y + c1 * acc[1].y + c2 * acc[2].y + c3 * acc[3].y;
    __syncwarp();

    float o0 = g_mx[(size_t)n * 64 + lane];
    float o1 = g_mx[(size_t)n * 64 + 32 + lane];
#pragma unroll
    for (int op = 0; op < 64; op++) {
        float gv = sGated[warp][op];
        o0 = fmaf(gv, sW2[op][lane], o0);
        o1 = fmaf(gv, sW2[op][lane + 32], o1);
    }
    out[n * 64 + lane] = o0;
    out[n * 64 + 32 + lane] = o1;
}

// ---------------- launch ----------------
extern "C" void kernel_launch(void* const* d_in, const int* in_sizes, int n_in,
                              void* d_out, int out_size) {
    const float* x         = (const float*)d_in[0];
    const int*   src       = (const int*)d_in[1];
    const int*   dst       = (const int*)d_in[2];
    const float* W_gat     = (const float*)d_in[3];
    const float* attn_l    = (const float*)d_in[4];
    const float* attn_r    = (const float*)d_in[5];
    const float* gate_m_W  = (const float*)d_in[6];
    const float* gate_m_b  = (const float*)d_in[7];
    const float* gate_fn_W = (const float*)d_in[8];
    const float* gate_fn_b = (const float*)d_in[9];
    const float* merge_W   = (const float*)d_in[10];
    const float* merge_b   = (const float*)d_in[11];
    float* out = (float*)d_out;

    k_prep<<<(KIN * NC + 255) / 256, 256>>>(W_gat, gate_m_W, gate_m_b, gate_fn_W,
                                            merge_W, merge_b, attn_l, attn_r);
    k_prep2<<<(NC * KIN + 255) / 256, 256>>>();
    k_split<<<(Nn * KIN / 4 + 255) / 256, 256>>>(x);
    k_deg<<<(Ee + 255) / 256, 256>>>(dst);
    k_scan<<<1, 1024>>>();
    k_fill<<<(Ee + 255) / 256, 256>>>(src, dst);
    dim3 ggrid(NC / 64, (Nn + 127) / 128);
    k_gemm_mma<<<ggrid, 256>>>();
    k_aggr<<<(Nn + 7) / 8, 256>>>(gate_fn_W, gate_fn_b, merge_W, out);
}